// round 1
// baseline (speedup 1.0000x reference)
#include <cuda_runtime.h>
#include <cstdint>

// Fixed problem geometry (from reference): N=100000 nodes, D=64 features.
#define N_NODES 100000
#define DIM     64

// Scratch (allocation-free rule: __device__ globals).
// g_h     : feature * norm_src, per node  [N, 64]
// g_accum : scatter-sum destination       [N, 64]
__device__ __align__(16) float g_h[N_NODES * DIM];
__device__ __align__(16) float g_accum[N_NODES * DIM];

// ---------------------------------------------------------------------------
// Kernel 1: h = feature * norm (per-node broadcast), accum = 0
// One thread per float4 (16 per node).
// ---------------------------------------------------------------------------
__global__ void prep_kernel(const float* __restrict__ feature,
                            const float* __restrict__ norm,
                            int n_vec4 /* = N*16 */) {
    int idx = blockIdx.x * blockDim.x + threadIdx.x;
    if (idx >= n_vec4) return;
    int node = idx >> 4;
    float nv = __ldg(norm + node);
    float4 f = reinterpret_cast<const float4*>(feature)[idx];
    f.x *= nv; f.y *= nv; f.z *= nv; f.w *= nv;
    reinterpret_cast<float4*>(g_h)[idx] = f;
    reinterpret_cast<float4*>(g_accum)[idx] = make_float4(0.f, 0.f, 0.f, 0.f);
}

// ---------------------------------------------------------------------------
// Kernel 2: edge scatter. 16 threads per edge; each does one float4 gather
// from g_h[src] and one vector reduction (red.global.add.v4.f32) into
// g_accum[dst]. Index loads are same-address within each 16-lane group
// (warp-level broadcast/coalesce).
// ---------------------------------------------------------------------------
__global__ void scatter_kernel(const int* __restrict__ src,
                               const int* __restrict__ dst,
                               int total /* = E*16 */) {
    int gid = blockIdx.x * blockDim.x + threadIdx.x;
    if (gid >= total) return;
    int e    = gid >> 4;
    int part = gid & 15;

    int s = __ldg(src + e);
    int d = __ldg(dst + e);

    float4 v = reinterpret_cast<const float4*>(g_h)[s * 16 + part];
    float* p = g_accum + ((long long)d * DIM + part * 4);

    asm volatile("red.global.add.v4.f32 [%0], {%1, %2, %3, %4};"
                 :: "l"(p), "f"(v.x), "f"(v.y), "f"(v.z), "f"(v.w)
                 : "memory");
}

// ---------------------------------------------------------------------------
// Kernel 3: out = (accum * norm) @ W^T + b
// Block = 256 threads = 64 nodes x 4 column-groups of 16.
// W transposed into shared as Wt[i][j] = W[j*64+i] so the inner loop does
// LDS.128 broadcasts (uniform address across the warp's replicated groups).
// ---------------------------------------------------------------------------
__global__ void linear_kernel(const float* __restrict__ norm,
                              const float* __restrict__ W,
                              const float* __restrict__ b,
                              float* __restrict__ out,
                              int n_nodes) {
    __shared__ float Wt[DIM * DIM];  // Wt[i*64 + j] = W[j*64 + i]
    __shared__ float bs[DIM];

    // Stage W (coalesced global read, transposed shared write) + bias.
    for (int k = threadIdx.x; k < DIM * DIM; k += blockDim.x) {
        int j = k >> 6;      // output col
        int i = k & 63;      // input col
        Wt[i * DIM + j] = W[k];
    }
    if (threadIdx.x < DIM) bs[threadIdx.x] = b[threadIdx.x];
    __syncthreads();

    int node = blockIdx.x * 64 + (threadIdx.x >> 2);
    int jg   = (threadIdx.x & 3) * 16;   // this thread's 16 output columns
    if (node >= n_nodes) return;

    float nv = __ldg(norm + node);

    float acc[16];
#pragma unroll
    for (int j = 0; j < 16; j++) acc[j] = bs[jg + j];

    const float4* arow = reinterpret_cast<const float4*>(g_accum + (long long)node * DIM);

#pragma unroll
    for (int i4 = 0; i4 < 16; i4++) {
        float4 a = arow[i4];
        a.x *= nv; a.y *= nv; a.z *= nv; a.w *= nv;
        const float av[4] = {a.x, a.y, a.z, a.w};
#pragma unroll
        for (int c = 0; c < 4; c++) {
            int i = i4 * 4 + c;
            const float4* wrow = reinterpret_cast<const float4*>(&Wt[i * DIM + jg]);
            float4 w0 = wrow[0], w1 = wrow[1], w2 = wrow[2], w3 = wrow[3];
            float a_i = av[c];
            acc[0]  = fmaf(a_i, w0.x, acc[0]);
            acc[1]  = fmaf(a_i, w0.y, acc[1]);
            acc[2]  = fmaf(a_i, w0.z, acc[2]);
            acc[3]  = fmaf(a_i, w0.w, acc[3]);
            acc[4]  = fmaf(a_i, w1.x, acc[4]);
            acc[5]  = fmaf(a_i, w1.y, acc[5]);
            acc[6]  = fmaf(a_i, w1.z, acc[6]);
            acc[7]  = fmaf(a_i, w1.w, acc[7]);
            acc[8]  = fmaf(a_i, w2.x, acc[8]);
            acc[9]  = fmaf(a_i, w2.y, acc[9]);
            acc[10] = fmaf(a_i, w2.z, acc[10]);
            acc[11] = fmaf(a_i, w2.w, acc[11]);
            acc[12] = fmaf(a_i, w3.x, acc[12]);
            acc[13] = fmaf(a_i, w3.y, acc[13]);
            acc[14] = fmaf(a_i, w3.z, acc[14]);
            acc[15] = fmaf(a_i, w3.w, acc[15]);
        }
    }

    float4* op = reinterpret_cast<float4*>(out + (long long)node * DIM + jg);
#pragma unroll
    for (int q = 0; q < 4; q++)
        op[q] = make_float4(acc[q * 4 + 0], acc[q * 4 + 1], acc[q * 4 + 2], acc[q * 4 + 3]);
}

// ---------------------------------------------------------------------------
// Launch: inputs in metadata order:
//   0: feature [N,64] f32   1: norm [N,1] f32   2: src [E] i32
//   3: dst [E] i32          4: W [64,64] f32    5: b [64] f32
// out: [N,64] f32
// ---------------------------------------------------------------------------
extern "C" void kernel_launch(void* const* d_in, const int* in_sizes, int n_in,
                              void* d_out, int out_size) {
    const float* feature = (const float*)d_in[0];
    const float* norm    = (const float*)d_in[1];
    const int*   src     = (const int*)d_in[2];
    const int*   dst     = (const int*)d_in[3];
    const float* W       = (const float*)d_in[4];
    const float* b       = (const float*)d_in[5];
    float*       out     = (float*)d_out;

    int n = in_sizes[1];           // N nodes (norm has N elements)
    int e = in_sizes[2];           // E edges

    int n_vec4 = n * 16;
    prep_kernel<<<(n_vec4 + 255) / 256, 256>>>(feature, norm, n_vec4);

    int total = e * 16;
    scatter_kernel<<<(total + 255) / 256, 256>>>(src, dst, total);

    linear_kernel<<<(n + 63) / 64, 256>>>(norm, W, b, out, n);
}

// round 2
// speedup vs baseline: 1.0601x; 1.0601x over previous
#include <cuda_runtime.h>
#include <cstdint>

#define N_NODES 100000
#define DIM     64
#define MAX_SCAN_BLOCKS 256   // supports up to 256*1024 nodes

// ---- scratch (allocation-free rule: __device__ globals) ----
__device__ __align__(16) float g_h[N_NODES * DIM];       // feature * norm_src
__device__ int g_count[N_NODES];                          // per-dst degree
__device__ int g_offset[N_NODES];                         // exclusive scan of count
__device__ int g_cursor[N_NODES];                         // fill cursors
__device__ int g_sorted_src[2000000];                     // src indices grouped by dst
__device__ int g_blocksums[MAX_SCAN_BLOCKS];

// ---------------------------------------------------------------------------
// K1: h = feature * norm ; zero degree counters
// ---------------------------------------------------------------------------
__global__ void prep_kernel(const float* __restrict__ feature,
                            const float* __restrict__ norm,
                            int n_vec4 /* = N*16 */) {
    int idx = blockIdx.x * blockDim.x + threadIdx.x;
    if (idx >= n_vec4) return;
    int node = idx >> 4;
    if ((idx & 15) == 0) g_count[node] = 0;
    float nv = __ldg(norm + node);
    float4 f = reinterpret_cast<const float4*>(feature)[idx];
    f.x *= nv; f.y *= nv; f.z *= nv; f.w *= nv;
    reinterpret_cast<float4*>(g_h)[idx] = f;
}

// ---------------------------------------------------------------------------
// K2: histogram of destinations
// ---------------------------------------------------------------------------
__global__ void hist_kernel(const int* __restrict__ dst, int e) {
    int i = blockIdx.x * blockDim.x + threadIdx.x;
    if (i < e) atomicAdd(&g_count[__ldg(dst + i)], 1);
}

// ---------------------------------------------------------------------------
// K3a/b/c: exclusive prefix sum over g_count -> g_offset (and init g_cursor)
// ---------------------------------------------------------------------------
__global__ void scan_block_kernel(int n) {
    __shared__ int sh[1024];
    int gid = blockIdx.x * 1024 + threadIdx.x;
    int v = (gid < n) ? g_count[gid] : 0;
    sh[threadIdx.x] = v;
    __syncthreads();
#pragma unroll
    for (int d = 1; d < 1024; d <<= 1) {
        int t = (threadIdx.x >= d) ? sh[threadIdx.x - d] : 0;
        __syncthreads();
        sh[threadIdx.x] += t;
        __syncthreads();
    }
    if (gid < n) g_offset[gid] = sh[threadIdx.x] - v;   // exclusive
    if (threadIdx.x == 1023) g_blocksums[blockIdx.x] = sh[1023];
}

__global__ void scan_sums_kernel(int nb) {
    __shared__ int sh[MAX_SCAN_BLOCKS];
    int v = (threadIdx.x < nb) ? g_blocksums[threadIdx.x] : 0;
    sh[threadIdx.x] = v;
    __syncthreads();
#pragma unroll
    for (int d = 1; d < MAX_SCAN_BLOCKS; d <<= 1) {
        int t = (threadIdx.x >= d) ? sh[threadIdx.x - d] : 0;
        __syncthreads();
        sh[threadIdx.x] += t;
        __syncthreads();
    }
    if (threadIdx.x < nb) g_blocksums[threadIdx.x] = sh[threadIdx.x] - v;  // exclusive
}

__global__ void scan_add_kernel(int n) {
    int gid = blockIdx.x * 1024 + threadIdx.x;
    if (gid < n) {
        int o = g_offset[gid] + g_blocksums[blockIdx.x];
        g_offset[gid] = o;
        g_cursor[gid] = o;
    }
}

// ---------------------------------------------------------------------------
// K4: bucket fill — group src indices by destination
// ---------------------------------------------------------------------------
__global__ void fill_kernel(const int* __restrict__ src,
                            const int* __restrict__ dst, int e) {
    int i = blockIdx.x * blockDim.x + threadIdx.x;
    if (i >= e) return;
    int d = __ldg(dst + i);
    int p = atomicAdd(&g_cursor[d], 1);
    g_sorted_src[p] = __ldg(src + i);
}

// ---------------------------------------------------------------------------
// K5 (fused): per-node gather-accumulate in registers, scale by norm[dst],
// stage row in shared, then 64x64 linear with f32x2 packed FMA.
// Block = 256 threads = 16 nodes (16 threads/node for gather,
//                        16 col-groups of 4 for the matmul).
// ---------------------------------------------------------------------------
__global__ void __launch_bounds__(256)
fused_gather_linear_kernel(const float* __restrict__ norm,
                           const float* __restrict__ W,
                           const float* __restrict__ b,
                           float* __restrict__ out,
                           int n) {
    __shared__ float sh_a[16][DIM];     // 16 node rows
    __shared__ float Wt[DIM * DIM];     // Wt[i*64+j] = W[j*64+i]
    __shared__ float bs[DIM];

    int tid = threadIdx.x;
    for (int k = tid; k < DIM * DIM; k += 256) {
        int j = k >> 6, i = k & 63;
        Wt[i * DIM + j] = W[k];
    }
    if (tid < DIM) bs[tid] = b[tid];

    int node_local = tid >> 4;
    int part       = tid & 15;
    int node       = blockIdx.x * 16 + node_local;

    // ---- gather-accumulate phase ----
    float4 acc = make_float4(0.f, 0.f, 0.f, 0.f);
    if (node < n) {
        int start = g_offset[node];
        int deg   = g_count[node];
        int end   = start + deg;
        const float4* h4 = reinterpret_cast<const float4*>(g_h);
        int k = start;
        for (; k + 4 <= end; k += 4) {
            int s0 = g_sorted_src[k + 0];
            int s1 = g_sorted_src[k + 1];
            int s2 = g_sorted_src[k + 2];
            int s3 = g_sorted_src[k + 3];
            float4 v0 = h4[s0 * 16 + part];
            float4 v1 = h4[s1 * 16 + part];
            float4 v2 = h4[s2 * 16 + part];
            float4 v3 = h4[s3 * 16 + part];
            acc.x += (v0.x + v1.x) + (v2.x + v3.x);
            acc.y += (v0.y + v1.y) + (v2.y + v3.y);
            acc.z += (v0.z + v1.z) + (v2.z + v3.z);
            acc.w += (v0.w + v1.w) + (v2.w + v3.w);
        }
        for (; k < end; k++) {
            int s = g_sorted_src[k];
            float4 v = h4[s * 16 + part];
            acc.x += v.x; acc.y += v.y; acc.z += v.z; acc.w += v.w;
        }
        float nv = __ldg(norm + node);
        acc.x *= nv; acc.y *= nv; acc.z *= nv; acc.w *= nv;
        reinterpret_cast<float4*>(&sh_a[node_local][0])[part] = acc;
    }
    __syncthreads();

    // ---- linear phase: out[node][jg..jg+3] ----
    if (node >= n) return;
    int jg = part * 4;

    unsigned long long a01, a23;
    asm("mov.b64 %0, {%1, %2};" : "=l"(a01) : "f"(bs[jg + 0]), "f"(bs[jg + 1]));
    asm("mov.b64 %0, {%1, %2};" : "=l"(a23) : "f"(bs[jg + 2]), "f"(bs[jg + 3]));

    const float* arow = &sh_a[node_local][0];
#pragma unroll 8
    for (int i = 0; i < DIM; i++) {
        float av = arow[i];
        unsigned long long aa;
        asm("mov.b64 %0, {%1, %1};" : "=l"(aa) : "f"(av));
        const ulonglong2* wp =
            reinterpret_cast<const ulonglong2*>(&Wt[i * DIM + jg]);
        ulonglong2 w = *wp;  // LDS.128, row-broadcast across half-warps
        asm("fma.rn.f32x2 %0, %1, %2, %0;" : "+l"(a01) : "l"(aa), "l"(w.x));
        asm("fma.rn.f32x2 %0, %1, %2, %0;" : "+l"(a23) : "l"(aa), "l"(w.y));
    }

    float r0, r1, r2, r3;
    asm("mov.b64 {%0, %1}, %2;" : "=f"(r0), "=f"(r1) : "l"(a01));
    asm("mov.b64 {%0, %1}, %2;" : "=f"(r2), "=f"(r3) : "l"(a23));
    reinterpret_cast<float4*>(out + (long long)node * DIM + jg)[0] =
        make_float4(r0, r1, r2, r3);
}

// ---------------------------------------------------------------------------
// Launch. Inputs: 0 feature [N,64] f32, 1 norm [N] f32, 2 src [E] i32,
//                 3 dst [E] i32, 4 W [64,64] f32, 5 b [64] f32. out [N,64] f32.
// ---------------------------------------------------------------------------
extern "C" void kernel_launch(void* const* d_in, const int* in_sizes, int n_in,
                              void* d_out, int out_size) {
    const float* feature = (const float*)d_in[0];
    const float* norm    = (const float*)d_in[1];
    const int*   src     = (const int*)d_in[2];
    const int*   dst     = (const int*)d_in[3];
    const float* W       = (const float*)d_in[4];
    const float* b       = (const float*)d_in[5];
    float*       out     = (float*)d_out;

    int n = in_sizes[1];   // nodes
    int e = in_sizes[2];   // edges

    int n_vec4 = n * 16;
    prep_kernel<<<(n_vec4 + 255) / 256, 256>>>(feature, norm, n_vec4);

    hist_kernel<<<(e + 511) / 512, 512>>>(dst, e);

    int nb = (n + 1023) / 1024;
    scan_block_kernel<<<nb, 1024>>>(n);
    scan_sums_kernel<<<1, MAX_SCAN_BLOCKS>>>(nb);
    scan_add_kernel<<<nb, 1024>>>(n);

    fill_kernel<<<(e + 511) / 512, 512>>>(src, dst, e);

    fused_gather_linear_kernel<<<(n + 15) / 16, 256>>>(norm, W, b, out, n);
}